// round 7
// baseline (speedup 1.0000x reference)
#include <cuda_runtime.h>
#include <cuda_fp16.h>
#include <cstdint>

// Problem constants
#define NE 8
#define ND 1024
#define NF 4096
#define NT 8192
#define NC 2048
#define NM (NE * NC)   // 16384 rows through the expert FFN

static constexpr float LO_SCALE = 2048.0f;       // 2^11: keeps lo planes normal fp16
static constexpr float INV_LO   = 1.0f / 2048.0f;

// ---------------- scratch (device globals; no runtime allocation) ----------
__device__ float g_scoresT[NE * NT];              // gates^T  [E, T]
__device__ int   g_idx[NM];                       // selected token ids [E*C]
__device__ float g_vals[NM];                      // routing probs of selected
__device__ __half g_xh[(size_t)NT * ND];          // x split hi (fp16)
__device__ __half g_xl[(size_t)NT * ND];          // x split lo * 2048
__device__ __half g_w1h[(size_t)NE * ND * NF];
__device__ __half g_w1l[(size_t)NE * ND * NF];
__device__ __half g_w2h[(size_t)NE * NF * ND];
__device__ __half g_w2l[(size_t)NE * NF * ND];
__device__ __half g_hh[(size_t)NM * NF];          // gelu output split hi
__device__ __half g_hl[(size_t)NM * NF];          // gelu output split lo * 2048

// ---------------- init output ------------------------------------------------
__global__ void init_out_kernel(float* out, size_t n_main, size_t total) {
    size_t i = (size_t)blockIdx.x * blockDim.x + threadIdx.x;
    size_t stride = (size_t)gridDim.x * blockDim.x;
    for (; i < total; i += stride) {
        if (i < n_main)       out[i] = 0.0f;
        else if (i == n_main) out[i] = 2.0f;   // aux_loss = E*(C/T)*1 = 2 analytically
        else                  out[i] = 0.0f;
    }
}

// ------------- fp32 -> (hi, lo*2048) fp16 split, 8 floats/thread ------------
__global__ void split_kernel(const float4* __restrict__ in,
                             uint4* __restrict__ hi,
                             uint4* __restrict__ lo, size_t n8) {
    size_t i = (size_t)blockIdx.x * blockDim.x + threadIdx.x;
    if (i >= n8) return;
    float4 a = in[2 * i];
    float4 b = in[2 * i + 1];
    float v[8] = {a.x, a.y, a.z, a.w, b.x, b.y, b.z, b.w};
    __half2 h[4], l[4];
#pragma unroll
    for (int j = 0; j < 4; j++) {
        float v0 = v[2 * j], v1 = v[2 * j + 1];
        __half h0 = __float2half_rn(v0);
        __half h1 = __float2half_rn(v1);
        h[j] = __halves2half2(h0, h1);
        l[j] = __floats2half2_rn((v0 - __half2float(h0)) * LO_SCALE,
                                 (v1 - __half2float(h1)) * LO_SCALE);
    }
    hi[i] = *(const uint4*)h;
    lo[i] = *(const uint4*)l;
}

// ---------------- router: gates = softmax(x @ Wg), stored transposed --------
__global__ void router_kernel(const float* __restrict__ x,
                              const float* __restrict__ Wg) {
    int warp = (blockIdx.x * blockDim.x + threadIdx.x) >> 5;
    int lane = threadIdx.x & 31;
    if (warp >= NT) return;
    const float* xr = x + (size_t)warp * ND;
    float acc[NE];
#pragma unroll
    for (int e = 0; e < NE; e++) acc[e] = 0.0f;
    for (int d = lane; d < ND; d += 32) {
        float xv = xr[d];
        const float4 w0 = *(const float4*)(Wg + d * NE);
        const float4 w1 = *(const float4*)(Wg + d * NE + 4);
        acc[0] += xv * w0.x; acc[1] += xv * w0.y;
        acc[2] += xv * w0.z; acc[3] += xv * w0.w;
        acc[4] += xv * w1.x; acc[5] += xv * w1.y;
        acc[6] += xv * w1.z; acc[7] += xv * w1.w;
    }
#pragma unroll
    for (int off = 16; off > 0; off >>= 1) {
#pragma unroll
        for (int e = 0; e < NE; e++)
            acc[e] += __shfl_down_sync(0xffffffffu, acc[e], off);
    }
    if (lane == 0) {
        float m = acc[0];
#pragma unroll
        for (int e = 1; e < NE; e++) m = fmaxf(m, acc[e]);
        float s = 0.0f;
#pragma unroll
        for (int e = 0; e < NE; e++) { acc[e] = expf(acc[e] - m); s += acc[e]; }
        float inv = 1.0f / s;
#pragma unroll
        for (int e = 0; e < NE; e++) g_scoresT[e * NT + warp] = acc[e] * inv;
    }
}

// ---------------- exact top-C per expert via 4-pass radix select ------------
__global__ void topk_kernel() {
    int e = blockIdx.x;
    int tid = threadIdx.x;
    const float* s = g_scoresT + e * NT;

    __shared__ unsigned hist[256];
    __shared__ unsigned sh_prefix;
    __shared__ int sh_rem;

    unsigned prefix = 0;
    int remaining = NC;

    for (int shift = 24; shift >= 0; shift -= 8) {
        if (tid < 256) hist[tid] = 0;
        __syncthreads();
        unsigned mask = (shift == 24) ? 0u : (0xFFFFFFFFu << (shift + 8));
        for (int t = tid; t < NT; t += blockDim.x) {
            unsigned k = __float_as_uint(s[t]);
            if ((k & mask) == prefix) atomicAdd(&hist[(k >> shift) & 0xFFu], 1u);
        }
        __syncthreads();
        if (tid == 0) {
            int rem = remaining;
            int b = 0;
            for (int d = 255; d >= 0; d--) {
                int h = (int)hist[d];
                if (h >= rem) { b = d; break; }
                rem -= h;
            }
            sh_prefix = prefix | ((unsigned)b << shift);
            sh_rem = rem;
        }
        __syncthreads();
        prefix = sh_prefix;
        remaining = sh_rem;
        __syncthreads();
    }

    __shared__ int cnt_gt, cnt_eq;
    if (tid == 0) { cnt_gt = 0; cnt_eq = 0; }
    __syncthreads();
    int base = NC - remaining;
    for (int t = tid; t < NT; t += blockDim.x) {
        unsigned k = __float_as_uint(s[t]);
        if (k > prefix) {
            int p = atomicAdd(&cnt_gt, 1);
            g_idx[e * NC + p]  = t;
            g_vals[e * NC + p] = s[t];
        } else if (k == prefix) {
            int p = atomicAdd(&cnt_eq, 1);
            if (p < remaining) {
                g_idx[e * NC + base + p]  = t;
                g_vals[e * NC + base + p] = s[t];
            }
        }
    }
}

// ---------------- gelu (tanh approx via fast exp; matches jax to ~1e-6) -----
__device__ __forceinline__ float gelu_f(float v) {
    float u = 0.7978845608028654f * (v + 0.044715f * v * v * v);
    float t = 1.0f - 2.0f / (__expf(2.0f * u) + 1.0f);
    return 0.5f * v * (1.0f + t);
}

// ====================== split-fp16 mma.sync GEMM ==============================
// CTA tile 128(M) x 256(N) x 32(K). 16 warps 4(m) x 4(n), warp tile 32x64.
// Main term hi*hi -> f32 accum; corrections lo*hi + hi*lo (lo pre-scaled by
// 2048) -> shared f16 accum at 2x HMMA rate; epilogue adds corr/2048.
// 3-stage cp.async pipeline.

static constexpr int A_STRIDE = 40;                 // fp16 units (80 B)
static constexpr int A_PLANE  = 128 * A_STRIDE;     // 5120
static constexpr int A_STAGE  = 2 * A_PLANE;        // hi + lo = 10240
static constexpr int B_BASE   = 3 * A_STAGE;        // 30720
static constexpr int B_STRIDE = 264;                // fp16 units (528 B)
static constexpr int B_PLANE  = 32 * B_STRIDE;      // 8448
static constexpr int B_STAGE  = 2 * B_PLANE;        // 16896
static constexpr int SMEM_F16 = B_BASE + 3 * B_STAGE;        // 81408
static constexpr int GEMM_SMEM_BYTES = SMEM_F16 * 2;         // 162816

__device__ __forceinline__ uint32_t smem_u32(const void* p) {
    uint32_t a;
    asm("{ .reg .u64 t; cvta.to.shared.u64 t, %1; cvt.u32.u64 %0, t; }"
        : "=r"(a) : "l"(p));
    return a;
}

__device__ __forceinline__ void cp16(uint32_t dst, const void* src) {
    asm volatile("cp.async.cg.shared.global [%0], [%1], 16;"
                 :: "r"(dst), "l"(src) : "memory");
}
#define CP_COMMIT() asm volatile("cp.async.commit_group;" ::: "memory")
#define CP_WAIT1()  asm volatile("cp.async.wait_group 1;" ::: "memory")

__device__ __forceinline__ void ldsm4(uint32_t* r, uint32_t addr) {
    asm volatile("ldmatrix.sync.aligned.m8n8.x4.shared.b16 {%0,%1,%2,%3}, [%4];"
                 : "=r"(r[0]), "=r"(r[1]), "=r"(r[2]), "=r"(r[3]) : "r"(addr));
}
__device__ __forceinline__ void ldsm4t(uint32_t* r, uint32_t addr) {
    asm volatile("ldmatrix.sync.aligned.m8n8.x4.trans.shared.b16 {%0,%1,%2,%3}, [%4];"
                 : "=r"(r[0]), "=r"(r[1]), "=r"(r[2]), "=r"(r[3]) : "r"(addr));
}

// main: fp16 inputs, fp32 accumulate
__device__ __forceinline__ void mma_f32(float* d, const uint32_t* a,
                                        const uint32_t* b) {
    asm volatile(
        "mma.sync.aligned.m16n8k16.row.col.f32.f16.f16.f32 "
        "{%0,%1,%2,%3}, {%4,%5,%6,%7}, {%8,%9}, {%0,%1,%2,%3};"
        : "+f"(d[0]), "+f"(d[1]), "+f"(d[2]), "+f"(d[3])
        : "r"(a[0]), "r"(a[1]), "r"(a[2]), "r"(a[3]), "r"(b[0]), "r"(b[1]));
}
// correction: fp16 inputs, fp16 accumulate (2x rate on legacy HMMA)
__device__ __forceinline__ void mma_f16(uint32_t* d, const uint32_t* a,
                                        const uint32_t* b) {
    asm volatile(
        "mma.sync.aligned.m16n8k16.row.col.f16.f16.f16.f16 "
        "{%0,%1}, {%2,%3,%4,%5}, {%6,%7}, {%0,%1};"
        : "+r"(d[0]), "+r"(d[1])
        : "r"(a[0]), "r"(a[1]), "r"(a[2]), "r"(a[3]), "r"(b[0]), "r"(b[1]));
}

__device__ __forceinline__ void red_v2(float* ptr, float v0, float v1) {
    asm volatile("red.global.add.v2.f32 [%0], {%1, %2};"
                 :: "l"(ptr), "f"(v0), "f"(v1) : "memory");
}

// NCH chunks of K=32 per CTA per K-slice. GATHER: A rows via g_idx (lda=ND).
// GELU_EPI: write split-fp16 gelu(acc+bias); else scatter-add into fp32 outa.
// blockIdx.z = K-slice; slice 0 adds bias. Ktot = full K (B expert stride).
template<int NCH, bool GATHER, bool GELU_EPI>
__global__ __launch_bounds__(512) void gemm_tc_kernel(
    const __half* __restrict__ Ah,
    const __half* __restrict__ Al,
    const __half* __restrict__ Bh,
    const __half* __restrict__ Bl,
    const float* __restrict__ bias,
    float* __restrict__ outa,
    __half* __restrict__ outbh,
    __half* __restrict__ outbl,
    int Nld, int lda, int Ktot) {
    extern __shared__ __align__(16) __half sm[];
    __shared__ int   tok_s[128];
    __shared__ float val_s[128];

    const int tid = threadIdx.x;
    const int warp = tid >> 5;
    const int lane = tid & 31;
    const int wm = warp >> 2;          // 0..3  (32-row slab)
    const int wn = warp & 3;           // 0..3  (64-col slab)
    const int r = lane >> 2;           // 0..7 (accumulator row)
    const int c = lane & 3;            // 0..3 (accumulator col pair)
    const int quad = lane >> 3;        // 0..3 (ldmatrix matrix id)
    const int r8 = lane & 7;           // row within 8x8 matrix

    const int n0 = blockIdx.x * 256;
    const int m0 = blockIdx.y * 128;
    const int e = m0 >> 11;            // m0 / NC
    const int kbase = blockIdx.z * NCH * 32;
    const bool bias_en = (blockIdx.z == 0);

    if (tid < 128) {
        tok_s[tid] = g_idx[m0 + tid];
        val_s[tid] = g_vals[m0 + tid];
    }
    __syncthreads();

    const uint32_t sbase = smem_u32(sm);

    // ---- precomputed load pointers (advance one K-chunk per load_stage) ----
    const __half* asrc[2];
    uint32_t adst0[2];
    const __half* bsrc[4];
    uint32_t bdst0[4];
    {
        const __half* aps[2] = {Ah, Al};
        const size_t bexp = (size_t)e * Ktot * Nld + n0;
        const __half* bps[2] = {Bh + bexp, Bl + bexp};
        const int arow = tid >> 2;
        const int aseg = (tid & 3) * 8;
#pragma unroll
        for (int p = 0; p < 2; p++) {
            asrc[p] = GATHER
                ? (aps[p] + (size_t)tok_s[arow] * lda + kbase + aseg)
                : (aps[p] + (size_t)(m0 + arow) * lda + kbase + aseg);
            adst0[p] = sbase + (uint32_t)(p * A_PLANE + arow * A_STRIDE + aseg) * 2;
#pragma unroll
            for (int i = 0; i < 2; i++) {
                int lin = tid + 512 * i;
                int row = lin >> 5;
                int seg = (lin & 31) * 8;
                int j = p * 2 + i;
                bsrc[j] = bps[p] + (size_t)(kbase + row) * Nld + seg;
                bdst0[j] = sbase + (uint32_t)(B_BASE + p * B_PLANE +
                                              row * B_STRIDE + seg) * 2;
            }
        }
    }

    auto load_stage = [&](int s) {
        const uint32_t ao = (uint32_t)s * (A_STAGE * 2);
        const uint32_t bo = (uint32_t)s * (B_STAGE * 2);
#pragma unroll
        for (int j = 0; j < 2; j++) {
            cp16(adst0[j] + ao, asrc[j]);
            asrc[j] += 32;
        }
#pragma unroll
        for (int j = 0; j < 4; j++) {
            cp16(bdst0[j] + bo, bsrc[j]);
            bsrc[j] += (size_t)32 * Nld;
        }
    };

    float acc[2][8][4];
    uint32_t cacc[2][8][2];            // f16x2 correction accumulators
#pragma unroll
    for (int mt = 0; mt < 2; mt++)
#pragma unroll
        for (int nt = 0; nt < 8; nt++) {
#pragma unroll
            for (int i = 0; i < 4; i++) acc[mt][nt][i] = 0.0f;
            cacc[mt][nt][0] = 0u;
            cacc[mt][nt][1] = 0u;
        }

    // prologue: fill stages 0, 1
    load_stage(0);
    CP_COMMIT();
    load_stage(1);
    CP_COMMIT();

#pragma unroll 1
    for (int ch = 0; ch < NCH; ch++) {
        const int s = ch % 3;
        CP_WAIT1();
        __syncthreads();
        if (ch + 2 < NCH) load_stage((ch + 2) % 3);
        CP_COMMIT();   // unconditional: keeps wait_group bookkeeping exact

        const uint32_t sa = sbase + (uint32_t)s * (A_STAGE * 2);
        const uint32_t sb = sbase + (uint32_t)(B_BASE * 2 + s * (B_STAGE * 2));
#pragma unroll
        for (int ks = 0; ks < 2; ks++) {
            // ---- A fragments: hi/lo x 2 m-tiles via ldmatrix.x4 ----
            uint32_t ah[2][4], al[2][4];
            {
                const int m_local = wm * 32 + (quad & 1) * 8 + r8;
                const int k_off = ks * 16 + (quad >> 1) * 8;
                const uint32_t abase = sa +
                    (uint32_t)(m_local * A_STRIDE + k_off) * 2;
#pragma unroll
                for (int mt = 0; mt < 2; mt++) {
                    ldsm4(ah[mt], abase + (uint32_t)(mt * 16 * A_STRIDE) * 2);
                    ldsm4(al[mt], abase + (uint32_t)(A_PLANE + mt * 16 * A_STRIDE) * 2);
                }
            }
            // ---- B fragments per 16-col group, then MMAs ----
            {
                const int k_row = ks * 16 + (quad & 1) * 8 + r8;
                const int n_col = wn * 64 + (quad >> 1) * 8;
                const uint32_t bbase = sb +
                    (uint32_t)(k_row * B_STRIDE + n_col) * 2;
#pragma unroll
                for (int nt2 = 0; nt2 < 4; nt2++) {
                    uint32_t bh[4], bl[4];
                    ldsm4t(bh, bbase + (uint32_t)(nt2 * 16) * 2);
                    ldsm4t(bl, bbase + (uint32_t)(B_PLANE + nt2 * 16) * 2);
                    const int nt = nt2 * 2;
#pragma unroll
                    for (int mt = 0; mt < 2; mt++) {
                        mma_f32(acc[mt][nt],      ah[mt], bh);       // hi*hi
                        mma_f16(cacc[mt][nt],     al[mt], bh);       // lo*hi
                        mma_f16(cacc[mt][nt],     ah[mt], bl);       // hi*lo
                        mma_f32(acc[mt][nt + 1],  ah[mt], bh + 2);
                        mma_f16(cacc[mt][nt + 1], al[mt], bh + 2);
                        mma_f16(cacc[mt][nt + 1], ah[mt], bl + 2);
                    }
                }
            }
        }
        __syncthreads();
    }

    // ---------------- epilogue -----------------------------------------------
#pragma unroll
    for (int mt = 0; mt < 2; mt++) {
        const int lm0 = wm * 32 + mt * 16 + r;       // local row of acc[0],acc[1]
        const int lm1 = lm0 + 8;                     // local row of acc[2],acc[3]
#pragma unroll
        for (int nt = 0; nt < 8; nt++) {
            const int bcol = n0 + wn * 64 + nt * 8 + c * 2;
            const float bb0 = bias_en ? bias[e * Nld + bcol] : 0.0f;
            const float bb1 = bias_en ? bias[e * Nld + bcol + 1] : 0.0f;
            float2 c01 = __half22float2(*(__half2*)&cacc[mt][nt][0]);
            float2 c23 = __half22float2(*(__half2*)&cacc[mt][nt][1]);
            float a0 = acc[mt][nt][0] + c01.x * INV_LO + bb0;
            float a1 = acc[mt][nt][1] + c01.y * INV_LO + bb1;
            float a2 = acc[mt][nt][2] + c23.x * INV_LO + bb0;
            float a3 = acc[mt][nt][3] + c23.y * INV_LO + bb1;
            if (GELU_EPI) {
                float v00 = gelu_f(a0);
                float v01 = gelu_f(a1);
                float v10 = gelu_f(a2);
                float v11 = gelu_f(a3);
                __half h00 = __float2half_rn(v00);
                __half h01 = __float2half_rn(v01);
                __half h10 = __float2half_rn(v10);
                __half h11 = __float2half_rn(v11);
                __half2 hp0 = __halves2half2(h00, h01);
                __half2 hp1 = __halves2half2(h10, h11);
                __half2 lp0 = __floats2half2_rn(
                    (v00 - __half2float(h00)) * LO_SCALE,
                    (v01 - __half2float(h01)) * LO_SCALE);
                __half2 lp1 = __floats2half2_rn(
                    (v10 - __half2float(h10)) * LO_SCALE,
                    (v11 - __half2float(h11)) * LO_SCALE);
                *(__half2*)(outbh + (size_t)(m0 + lm0) * Nld + bcol) = hp0;
                *(__half2*)(outbh + (size_t)(m0 + lm1) * Nld + bcol) = hp1;
                *(__half2*)(outbl + (size_t)(m0 + lm0) * Nld + bcol) = lp0;
                *(__half2*)(outbl + (size_t)(m0 + lm1) * Nld + bcol) = lp1;
            } else {
                const float w0 = val_s[lm0];
                const float w1 = val_s[lm1];
                float* p0 = outa + (size_t)tok_s[lm0] * ND + bcol;
                float* p1 = outa + (size_t)tok_s[lm1] * ND + bcol;
                red_v2(p0, a0 * w0, a1 * w0);
                red_v2(p1, a2 * w1, a3 * w1);
            }
        }
    }
}

// ============================ host launch =====================================
extern "C" void kernel_launch(void* const* d_in, const int* in_sizes, int n_in,
                              void* d_out, int out_size) {
    const float* x  = (const float*)d_in[0];   // [T, D]
    const float* Wg = (const float*)d_in[1];   // [D, E]
    const float* W1 = (const float*)d_in[2];   // [E, D, F]
    const float* b1 = (const float*)d_in[3];   // [E, F]
    const float* W2 = (const float*)d_in[4];   // [E, F, D]
    const float* b2 = (const float*)d_in[5];   // [E, D]
    float* out = (float*)d_out;

    void *p_xh, *p_xl, *p_w1h, *p_w1l, *p_w2h, *p_w2l, *p_hh, *p_hl;
    cudaGetSymbolAddress(&p_xh, g_xh);
    cudaGetSymbolAddress(&p_xl, g_xl);
    cudaGetSymbolAddress(&p_w1h, g_w1h);
    cudaGetSymbolAddress(&p_w1l, g_w1l);
    cudaGetSymbolAddress(&p_w2h, g_w2h);
    cudaGetSymbolAddress(&p_w2l, g_w2l);
    cudaGetSymbolAddress(&p_hh, g_hh);
    cudaGetSymbolAddress(&p_hl, g_hl);

    cudaFuncSetAttribute((const void*)gemm_tc_kernel<32, true, true>,
                         cudaFuncAttributeMaxDynamicSharedMemorySize,
                         GEMM_SMEM_BYTES);
    cudaFuncSetAttribute((const void*)gemm_tc_kernel<64, false, false>,
                         cudaFuncAttributeMaxDynamicSharedMemorySize,
                         GEMM_SMEM_BYTES);

    size_t n_main = (size_t)NT * ND;
    init_out_kernel<<<512, 256>>>(out, n_main, (size_t)out_size);
    router_kernel<<<NT / 32, 1024>>>(x, Wg);
    topk_kernel<<<NE, 1024>>>();

    // Pre-split operands into fp16 hi / scaled-lo planes, 8 floats/thread.
    split_kernel<<<(NT * ND / 8 + 255) / 256, 256>>>(
        (const float4*)x, (uint4*)p_xh, (uint4*)p_xl, (size_t)NT * ND / 8);
    split_kernel<<<((size_t)NE * ND * NF / 8 + 255) / 256, 256>>>(
        (const float4*)W1, (uint4*)p_w1h, (uint4*)p_w1l,
        (size_t)NE * ND * NF / 8);
    split_kernel<<<((size_t)NE * NF * ND / 8 + 255) / 256, 256>>>(
        (const float4*)W2, (uint4*)p_w2h, (uint4*)p_w2l,
        (size_t)NE * NF * ND / 8);

    // GEMM1: h = gelu(x[idx] @ W1[e] + b1[e])   M=16384, N=4096, K=1024
    gemm_tc_kernel<32, true, true>
        <<<dim3(NF / 256, NM / 128, 1), 512, GEMM_SMEM_BYTES>>>(
            (const __half*)p_xh, (const __half*)p_xl,
            (const __half*)p_w1h, (const __half*)p_w1l,
            b1, nullptr,
            (__half*)p_hh, (__half*)p_hl, NF, ND, ND);

    // GEMM2: out[tok] += val*(h @ W2[e] + b2[e])  M=16384, N=1024, K=4096
    // split-K = 2 (epilogue is scatter-add, so K-slices both reduce in)
    gemm_tc_kernel<64, false, false>
        <<<dim3(ND / 256, NM / 128, 2), 512, GEMM_SMEM_BYTES>>>(
            (const __half*)p_hh, (const __half*)p_hl,
            (const __half*)p_w2h, (const __half*)p_w2l,
            b2, out, nullptr, nullptr, ND, NF, NF);
}

// round 8
// speedup vs baseline: 1.2287x; 1.2287x over previous
#include <cuda_runtime.h>
#include <cuda_bf16.h>
#include <cstdint>

// Problem constants
#define NE 8
#define ND 1024
#define NF 4096
#define NT 8192
#define NC 2048
#define NM (NE * NC)   // 16384 rows through the expert FFN

// ---------------- scratch (device globals; no runtime allocation) ----------
__device__ float g_scoresT[NE * NT];              // gates^T  [E, T]
__device__ int   g_idx[NM];                       // selected token ids [E*C]
__device__ float g_vals[NM];                      // routing probs of selected
__device__ __nv_bfloat16 g_xh[(size_t)NT * ND];   // x split hi
__device__ __nv_bfloat16 g_xl[(size_t)NT * ND];   // x split lo
__device__ __nv_bfloat16 g_w1h[(size_t)NE * ND * NF];
__device__ __nv_bfloat16 g_w1l[(size_t)NE * ND * NF];
__device__ __nv_bfloat16 g_w2h[(size_t)NE * NF * ND];
__device__ __nv_bfloat16 g_w2l[(size_t)NE * NF * ND];
__device__ __nv_bfloat16 g_hh[(size_t)NM * NF];   // gelu output split hi
__device__ __nv_bfloat16 g_hl[(size_t)NM * NF];   // gelu output split lo

// ---------------- init output ------------------------------------------------
__global__ void init_out_kernel(float* out, size_t n_main, size_t total) {
    size_t i = (size_t)blockIdx.x * blockDim.x + threadIdx.x;
    size_t stride = (size_t)gridDim.x * blockDim.x;
    for (; i < total; i += stride) {
        if (i < n_main)       out[i] = 0.0f;
        else if (i == n_main) out[i] = 2.0f;   // aux_loss = E*(C/T)*1 = 2 analytically
        else                  out[i] = 0.0f;
    }
}

// ---------------- fp32 -> (hi, lo) bf16 split, 8 floats/thread --------------
__global__ void split_kernel(const float4* __restrict__ in,
                             uint4* __restrict__ hi,
                             uint4* __restrict__ lo, size_t n8) {
    size_t i = (size_t)blockIdx.x * blockDim.x + threadIdx.x;
    if (i >= n8) return;
    float4 a = in[2 * i];
    float4 b = in[2 * i + 1];
    __nv_bfloat162 h[4], l[4];
    h[0] = __floats2bfloat162_rn(a.x, a.y);
    h[1] = __floats2bfloat162_rn(a.z, a.w);
    h[2] = __floats2bfloat162_rn(b.x, b.y);
    h[3] = __floats2bfloat162_rn(b.z, b.w);
    l[0] = __floats2bfloat162_rn(a.x - __bfloat162float(h[0].x),
                                 a.y - __bfloat162float(h[0].y));
    l[1] = __floats2bfloat162_rn(a.z - __bfloat162float(h[1].x),
                                 a.w - __bfloat162float(h[1].y));
    l[2] = __floats2bfloat162_rn(b.x - __bfloat162float(h[2].x),
                                 b.y - __bfloat162float(h[2].y));
    l[3] = __floats2bfloat162_rn(b.z - __bfloat162float(h[3].x),
                                 b.w - __bfloat162float(h[3].y));
    hi[i] = *(const uint4*)h;
    lo[i] = *(const uint4*)l;
}

// ---------------- router: gates = softmax(x @ Wg), stored transposed --------
__global__ void router_kernel(const float* __restrict__ x,
                              const float* __restrict__ Wg) {
    int warp = (blockIdx.x * blockDim.x + threadIdx.x) >> 5;
    int lane = threadIdx.x & 31;
    if (warp >= NT) return;
    const float* xr = x + (size_t)warp * ND;
    float acc[NE];
#pragma unroll
    for (int e = 0; e < NE; e++) acc[e] = 0.0f;
    for (int d = lane; d < ND; d += 32) {
        float xv = xr[d];
        const float4 w0 = *(const float4*)(Wg + d * NE);
        const float4 w1 = *(const float4*)(Wg + d * NE + 4);
        acc[0] += xv * w0.x; acc[1] += xv * w0.y;
        acc[2] += xv * w0.z; acc[3] += xv * w0.w;
        acc[4] += xv * w1.x; acc[5] += xv * w1.y;
        acc[6] += xv * w1.z; acc[7] += xv * w1.w;
    }
#pragma unroll
    for (int off = 16; off > 0; off >>= 1) {
#pragma unroll
        for (int e = 0; e < NE; e++)
            acc[e] += __shfl_down_sync(0xffffffffu, acc[e], off);
    }
    if (lane == 0) {
        float m = acc[0];
#pragma unroll
        for (int e = 1; e < NE; e++) m = fmaxf(m, acc[e]);
        float s = 0.0f;
#pragma unroll
        for (int e = 0; e < NE; e++) { acc[e] = expf(acc[e] - m); s += acc[e]; }
        float inv = 1.0f / s;
#pragma unroll
        for (int e = 0; e < NE; e++) g_scoresT[e * NT + warp] = acc[e] * inv;
    }
}

// ---------------- exact top-C per expert via 4-pass radix select ------------
__global__ void topk_kernel() {
    int e = blockIdx.x;
    int tid = threadIdx.x;
    const float* s = g_scoresT + e * NT;

    __shared__ unsigned hist[256];
    __shared__ unsigned sh_prefix;
    __shared__ int sh_rem;

    unsigned prefix = 0;
    int remaining = NC;

    for (int shift = 24; shift >= 0; shift -= 8) {
        if (tid < 256) hist[tid] = 0;
        __syncthreads();
        unsigned mask = (shift == 24) ? 0u : (0xFFFFFFFFu << (shift + 8));
        for (int t = tid; t < NT; t += blockDim.x) {
            unsigned k = __float_as_uint(s[t]);
            if ((k & mask) == prefix) atomicAdd(&hist[(k >> shift) & 0xFFu], 1u);
        }
        __syncthreads();
        if (tid == 0) {
            int rem = remaining;
            int b = 0;
            for (int d = 255; d >= 0; d--) {
                int h = (int)hist[d];
                if (h >= rem) { b = d; break; }
                rem -= h;
            }
            sh_prefix = prefix | ((unsigned)b << shift);
            sh_rem = rem;
        }
        __syncthreads();
        prefix = sh_prefix;
        remaining = sh_rem;
        __syncthreads();
    }

    __shared__ int cnt_gt, cnt_eq;
    if (tid == 0) { cnt_gt = 0; cnt_eq = 0; }
    __syncthreads();
    int base = NC - remaining;
    for (int t = tid; t < NT; t += blockDim.x) {
        unsigned k = __float_as_uint(s[t]);
        if (k > prefix) {
            int p = atomicAdd(&cnt_gt, 1);
            g_idx[e * NC + p]  = t;
            g_vals[e * NC + p] = s[t];
        } else if (k == prefix) {
            int p = atomicAdd(&cnt_eq, 1);
            if (p < remaining) {
                g_idx[e * NC + base + p]  = t;
                g_vals[e * NC + base + p] = s[t];
            }
        }
    }
}

// ---------------- gelu (tanh approx via fast exp; matches jax to ~1e-6) -----
__device__ __forceinline__ float gelu_f(float v) {
    float u = 0.7978845608028654f * (v + 0.044715f * v * v * v);
    float t = 1.0f - 2.0f / (__expf(2.0f * u) + 1.0f);
    return 0.5f * v * (1.0f + t);
}

// ============================ 3xBF16 mma.sync GEMM ============================
// CTA tile 128(M) x 256(N) x 32(K). 512 threads, 16 warps 2(m) x 8(n),
// warp tile 64x32. hi*hi + lo*hi + hi*lo on m16n8k16.bf16, all f32 accum.
// 3-stage cp.async pipeline. 4 warps/SMSP for HMMA latency hiding.

static constexpr int A_STRIDE = 40;                 // bf16 units (80 B)
static constexpr int A_PLANE  = 128 * A_STRIDE;     // 5120
static constexpr int A_STAGE  = 2 * A_PLANE;        // hi + lo = 10240
static constexpr int B_BASE   = 3 * A_STAGE;        // 30720
static constexpr int B_STRIDE = 264;                // bf16 units (528 B)
static constexpr int B_PLANE  = 32 * B_STRIDE;      // 8448
static constexpr int B_STAGE  = 2 * B_PLANE;        // 16896
static constexpr int SMEM_BF16 = B_BASE + 3 * B_STAGE;       // 81408
static constexpr int GEMM_SMEM_BYTES = SMEM_BF16 * 2;        // 162816

__device__ __forceinline__ uint32_t smem_u32(const void* p) {
    uint32_t a;
    asm("{ .reg .u64 t; cvta.to.shared.u64 t, %1; cvt.u32.u64 %0, t; }"
        : "=r"(a) : "l"(p));
    return a;
}

__device__ __forceinline__ void cp16(uint32_t dst, const void* src) {
    asm volatile("cp.async.cg.shared.global [%0], [%1], 16;"
                 :: "r"(dst), "l"(src) : "memory");
}
#define CP_COMMIT() asm volatile("cp.async.commit_group;" ::: "memory")
#define CP_WAIT1()  asm volatile("cp.async.wait_group 1;" ::: "memory")

__device__ __forceinline__ void ldsm4(uint32_t* r, uint32_t addr) {
    asm volatile("ldmatrix.sync.aligned.m8n8.x4.shared.b16 {%0,%1,%2,%3}, [%4];"
                 : "=r"(r[0]), "=r"(r[1]), "=r"(r[2]), "=r"(r[3]) : "r"(addr));
}
__device__ __forceinline__ void ldsm4t(uint32_t* r, uint32_t addr) {
    asm volatile("ldmatrix.sync.aligned.m8n8.x4.trans.shared.b16 {%0,%1,%2,%3}, [%4];"
                 : "=r"(r[0]), "=r"(r[1]), "=r"(r[2]), "=r"(r[3]) : "r"(addr));
}

__device__ __forceinline__ void mma_bf16(float* d, const uint32_t* a,
                                         const uint32_t* b) {
    asm volatile(
        "mma.sync.aligned.m16n8k16.row.col.f32.bf16.bf16.f32 "
        "{%0,%1,%2,%3}, {%4,%5,%6,%7}, {%8,%9}, {%0,%1,%2,%3};"
        : "+f"(d[0]), "+f"(d[1]), "+f"(d[2]), "+f"(d[3])
        : "r"(a[0]), "r"(a[1]), "r"(a[2]), "r"(a[3]), "r"(b[0]), "r"(b[1]));
}

__device__ __forceinline__ void red_v2(float* ptr, float v0, float v1) {
    asm volatile("red.global.add.v2.f32 [%0], {%1, %2};"
                 :: "l"(ptr), "f"(v0), "f"(v1) : "memory");
}

// NCH chunks of K=32 per CTA per K-slice. GATHER: A rows via g_idx (lda=ND).
// GELU_EPI: write split-bf16 gelu(acc+bias); else scatter-add into fp32 outa.
// blockIdx.z = K-slice; slice 0 adds bias. Ktot = full K (B expert stride).
template<int NCH, bool GATHER, bool GELU_EPI>
__global__ __launch_bounds__(512) void gemm_tc_kernel(
    const __nv_bfloat16* __restrict__ Ah,
    const __nv_bfloat16* __restrict__ Al,
    const __nv_bfloat16* __restrict__ Bh,
    const __nv_bfloat16* __restrict__ Bl,
    const float* __restrict__ bias,
    float* __restrict__ outa,
    __nv_bfloat16* __restrict__ outbh,
    __nv_bfloat16* __restrict__ outbl,
    int Nld, int lda, int Ktot) {
    extern __shared__ __align__(16) __nv_bfloat16 sm[];
    __shared__ int   tok_s[128];
    __shared__ float val_s[128];

    const int tid = threadIdx.x;
    const int warp = tid >> 5;
    const int lane = tid & 31;
    const int wm = warp >> 3;          // 0..1  (64-row slab)
    const int wn = warp & 7;           // 0..7  (32-col slab)
    const int r = lane >> 2;           // 0..7 (accumulator row)
    const int c = lane & 3;            // 0..3 (accumulator col pair)
    const int quad = lane >> 3;        // 0..3 (ldmatrix matrix id)
    const int r8 = lane & 7;           // row within 8x8 matrix

    const int n0 = blockIdx.x * 256;
    const int m0 = blockIdx.y * 128;
    const int e = m0 >> 11;            // m0 / NC
    const int kbase = blockIdx.z * NCH * 32;
    const bool bias_en = (blockIdx.z == 0);

    if (tid < 128) {
        tok_s[tid] = g_idx[m0 + tid];
        val_s[tid] = g_vals[m0 + tid];
    }
    __syncthreads();

    const uint32_t sbase = smem_u32(sm);

    // ---- precomputed load pointers (advance one K-chunk per load_stage) ----
    const __nv_bfloat16* asrc[2];
    uint32_t adst0[2];
    const __nv_bfloat16* bsrc[4];
    uint32_t bdst0[4];
    {
        const __nv_bfloat16* aps[2] = {Ah, Al};
        const size_t bexp = (size_t)e * Ktot * Nld + n0;
        const __nv_bfloat16* bps[2] = {Bh + bexp, Bl + bexp};
        const int arow = tid >> 2;
        const int aseg = (tid & 3) * 8;
#pragma unroll
        for (int p = 0; p < 2; p++) {
            asrc[p] = GATHER
                ? (aps[p] + (size_t)tok_s[arow] * lda + kbase + aseg)
                : (aps[p] + (size_t)(m0 + arow) * lda + kbase + aseg);
            adst0[p] = sbase + (uint32_t)(p * A_PLANE + arow * A_STRIDE + aseg) * 2;
#pragma unroll
            for (int i = 0; i < 2; i++) {
                int lin = tid + 512 * i;
                int row = lin >> 5;
                int seg = (lin & 31) * 8;
                int j = p * 2 + i;
                bsrc[j] = bps[p] + (size_t)(kbase + row) * Nld + seg;
                bdst0[j] = sbase + (uint32_t)(B_BASE + p * B_PLANE +
                                              row * B_STRIDE + seg) * 2;
            }
        }
    }

    auto load_stage = [&](int s) {
        const uint32_t ao = (uint32_t)s * (A_STAGE * 2);
        const uint32_t bo = (uint32_t)s * (B_STAGE * 2);
#pragma unroll
        for (int j = 0; j < 2; j++) {
            cp16(adst0[j] + ao, asrc[j]);
            asrc[j] += 32;
        }
#pragma unroll
        for (int j = 0; j < 4; j++) {
            cp16(bdst0[j] + bo, bsrc[j]);
            bsrc[j] += (size_t)32 * Nld;
        }
    };

    float acc[4][4][4];                // [mt][nt][frag]
#pragma unroll
    for (int mt = 0; mt < 4; mt++)
#pragma unroll
        for (int nt = 0; nt < 4; nt++)
#pragma unroll
            for (int i = 0; i < 4; i++) acc[mt][nt][i] = 0.0f;

    // prologue: fill stages 0, 1
    load_stage(0);
    CP_COMMIT();
    load_stage(1);
    CP_COMMIT();

#pragma unroll 1
    for (int ch = 0; ch < NCH; ch++) {
        const int s = ch % 3;
        CP_WAIT1();
        __syncthreads();
        if (ch + 2 < NCH) load_stage((ch + 2) % 3);
        CP_COMMIT();   // unconditional: keeps wait_group bookkeeping exact

        const uint32_t sa = sbase + (uint32_t)s * (A_STAGE * 2);
        const uint32_t sb = sbase + (uint32_t)(B_BASE * 2 + s * (B_STAGE * 2));
#pragma unroll
        for (int ks = 0; ks < 2; ks++) {
            // ---- A fragments: hi/lo x 4 m-tiles via ldmatrix.x4 ----
            uint32_t ah[4][4], al[4][4];
            {
                const int m_local = wm * 64 + (quad & 1) * 8 + r8;
                const int k_off = ks * 16 + (quad >> 1) * 8;
                const uint32_t abase = sa +
                    (uint32_t)(m_local * A_STRIDE + k_off) * 2;
#pragma unroll
                for (int mt = 0; mt < 4; mt++) {
                    ldsm4(ah[mt], abase + (uint32_t)(mt * 16 * A_STRIDE) * 2);
                    ldsm4(al[mt], abase + (uint32_t)(A_PLANE + mt * 16 * A_STRIDE) * 2);
                }
            }
            // ---- B fragments per 16-col group, then MMAs ----
            {
                const int k_row = ks * 16 + (quad & 1) * 8 + r8;
                const int n_col = wn * 32 + (quad >> 1) * 8;
                const uint32_t bbase = sb +
                    (uint32_t)(k_row * B_STRIDE + n_col) * 2;
#pragma unroll
                for (int nt2 = 0; nt2 < 2; nt2++) {
                    uint32_t bh[4], bl[4];
                    ldsm4t(bh, bbase + (uint32_t)(nt2 * 16) * 2);
                    ldsm4t(bl, bbase + (uint32_t)(B_PLANE + nt2 * 16) * 2);
                    const int nt = nt2 * 2;
#pragma unroll
                    for (int mt = 0; mt < 4; mt++) {
                        mma_bf16(acc[mt][nt],     ah[mt], bh);        // hi*hi
                        mma_bf16(acc[mt][nt],     al[mt], bh);        // lo*hi
                        mma_bf16(acc[mt][nt],     ah[mt], bl);        // hi*lo
                        mma_bf16(acc[mt][nt + 1], ah[mt], bh + 2);
                        mma_bf16(acc[mt][nt + 1], al[mt], bh + 2);
                        mma_bf16(acc[mt][nt + 1], ah[mt], bl + 2);
                    }
                }
            }
        }
        __syncthreads();
    }

    // ---------------- epilogue -----------------------------------------------
#pragma unroll
    for (int mt = 0; mt < 4; mt++) {
        const int lm0 = wm * 64 + mt * 16 + r;       // local row of acc[0],acc[1]
        const int lm1 = lm0 + 8;                     // local row of acc[2],acc[3]
#pragma unroll
        for (int nt = 0; nt < 4; nt++) {
            const int bcol = n0 + wn * 32 + nt * 8 + c * 2;
            const float bb0 = bias_en ? bias[e * Nld + bcol] : 0.0f;
            const float bb1 = bias_en ? bias[e * Nld + bcol + 1] : 0.0f;
            if (GELU_EPI) {
                float v00 = gelu_f(acc[mt][nt][0] + bb0);
                float v01 = gelu_f(acc[mt][nt][1] + bb1);
                float v10 = gelu_f(acc[mt][nt][2] + bb0);
                float v11 = gelu_f(acc[mt][nt][3] + bb1);
                __nv_bfloat162 h0, h1, l0, l1;
                h0.x = __float2bfloat16_rn(v00);
                h0.y = __float2bfloat16_rn(v01);
                h1.x = __float2bfloat16_rn(v10);
                h1.y = __float2bfloat16_rn(v11);
                l0.x = __float2bfloat16_rn(v00 - __bfloat162float(h0.x));
                l0.y = __float2bfloat16_rn(v01 - __bfloat162float(h0.y));
                l1.x = __float2bfloat16_rn(v10 - __bfloat162float(h1.x));
                l1.y = __float2bfloat16_rn(v11 - __bfloat162float(h1.y));
                *(__nv_bfloat162*)(outbh + (size_t)(m0 + lm0) * Nld + bcol) = h0;
                *(__nv_bfloat162*)(outbh + (size_t)(m0 + lm1) * Nld + bcol) = h1;
                *(__nv_bfloat162*)(outbl + (size_t)(m0 + lm0) * Nld + bcol) = l0;
                *(__nv_bfloat162*)(outbl + (size_t)(m0 + lm1) * Nld + bcol) = l1;
            } else {
                const float w0 = val_s[lm0];
                const float w1 = val_s[lm1];
                float* p0 = outa + (size_t)tok_s[lm0] * ND + bcol;
                float* p1 = outa + (size_t)tok_s[lm1] * ND + bcol;
                red_v2(p0, (acc[mt][nt][0] + bb0) * w0, (acc[mt][nt][1] + bb1) * w0);
                red_v2(p1, (acc[mt][nt][2] + bb0) * w1, (acc[mt][nt][3] + bb1) * w1);
            }
        }
    }
}

// ============================ host launch =====================================
extern "C" void kernel_launch(void* const* d_in, const int* in_sizes, int n_in,
                              void* d_out, int out_size) {
    const float* x  = (const float*)d_in[0];   // [T, D]
    const float* Wg = (const float*)d_in[1];   // [D, E]
    const float* W1 = (const float*)d_in[2];   // [E, D, F]
    const float* b1 = (const float*)d_in[3];   // [E, F]
    const float* W2 = (const float*)d_in[4];   // [E, F, D]
    const float* b2 = (const float*)d_in[5];   // [E, D]
    float* out = (float*)d_out;

    void *p_xh, *p_xl, *p_w1h, *p_w1l, *p_w2h, *p_w2l, *p_hh, *p_hl;
    cudaGetSymbolAddress(&p_xh, g_xh);
    cudaGetSymbolAddress(&p_xl, g_xl);
    cudaGetSymbolAddress(&p_w1h, g_w1h);
    cudaGetSymbolAddress(&p_w1l, g_w1l);
    cudaGetSymbolAddress(&p_w2h, g_w2h);
    cudaGetSymbolAddress(&p_w2l, g_w2l);
    cudaGetSymbolAddress(&p_hh, g_hh);
    cudaGetSymbolAddress(&p_hl, g_hl);

    cudaFuncSetAttribute((const void*)gemm_tc_kernel<32, true, true>,
                         cudaFuncAttributeMaxDynamicSharedMemorySize,
                         GEMM_SMEM_BYTES);
    cudaFuncSetAttribute((const void*)gemm_tc_kernel<64, false, false>,
                         cudaFuncAttributeMaxDynamicSharedMemorySize,
                         GEMM_SMEM_BYTES);

    size_t n_main = (size_t)NT * ND;
    init_out_kernel<<<512, 256>>>(out, n_main, (size_t)out_size);
    router_kernel<<<NT / 32, 1024>>>(x, Wg);
    topk_kernel<<<NE, 1024>>>();

    // Pre-split operands into bf16 hi/lo planes, 8 floats/thread.
    split_kernel<<<(NT * ND / 8 + 255) / 256, 256>>>(
        (const float4*)x, (uint4*)p_xh, (uint4*)p_xl, (size_t)NT * ND / 8);
    split_kernel<<<((size_t)NE * ND * NF / 8 + 255) / 256, 256>>>(
        (const float4*)W1, (uint4*)p_w1h, (uint4*)p_w1l,
        (size_t)NE * ND * NF / 8);
    split_kernel<<<((size_t)NE * NF * ND / 8 + 255) / 256, 256>>>(
        (const float4*)W2, (uint4*)p_w2h, (uint4*)p_w2l,
        (size_t)NE * NF * ND / 8);

    // GEMM1: h = gelu(x[idx] @ W1[e] + b1[e])   M=16384, N=4096, K=1024
    gemm_tc_kernel<32, true, true>
        <<<dim3(NF / 256, NM / 128, 1), 512, GEMM_SMEM_BYTES>>>(
            (const __nv_bfloat16*)p_xh, (const __nv_bfloat16*)p_xl,
            (const __nv_bfloat16*)p_w1h, (const __nv_bfloat16*)p_w1l,
            b1, nullptr,
            (__nv_bfloat16*)p_hh, (__nv_bfloat16*)p_hl, NF, ND, ND);

    // GEMM2: out[tok] += val*(h @ W2[e] + b2[e])  M=16384, N=1024, K=4096
    // split-K = 2 (epilogue is scatter-add, so K-slices both reduce in)
    gemm_tc_kernel<64, false, false>
        <<<dim3(ND / 256, NM / 128, 2), 512, GEMM_SMEM_BYTES>>>(
            (const __nv_bfloat16*)p_hh, (const __nv_bfloat16*)p_hl,
            (const __nv_bfloat16*)p_w2h, (const __nv_bfloat16*)p_w2l,
            b2, out, nullptr, nullptr, ND, NF, NF);
}